// round 1
// baseline (speedup 1.0000x reference)
#include <cuda_runtime.h>
#include <math.h>
#include <stdint.h>

// ---------------- problem constants ----------------
#define B_   512
#define NW   64
#define NQ   343            // window tokens
#define GTN  1
#define NTOK 344            // NQ + GTN
#define DIM  96
#define H    3
#define HD   32
#define TBL  2197           // (2*7-1)^3

#define NROWS (B_*NTOK)     // 176128
#define XOUT_SZ ((size_t)B_*NQ*DIM)

// ---------------- scratch (device globals; no cudaMalloc allowed) -------
__device__ float g_q[(size_t)B_*H*NTOK*HD];
__device__ float g_k[(size_t)B_*H*NTOK*HD];
__device__ float g_v[(size_t)B_*H*NTOK*HD];
__device__ float g_att[(size_t)B_*NTOK*DIM];
__device__ float g_bias[(size_t)H*NQ*NQ];

// ---------------- kernel 0: bias gather ----------------
__global__ void bias_pre_kernel(const float* __restrict__ btab,
                                const int* __restrict__ ri) {
    int idx = blockIdx.x * 256 + threadIdx.x;
    if (idx < NQ*NQ) {
        int r = ri[idx];
        #pragma unroll
        for (int h = 0; h < H; ++h)
            g_bias[(size_t)h*NQ*NQ + idx] = btab[r*H + h];
    }
}

// ---------------- kernel 1: qkv = xc @ Wqkv^T + b ----------------
// grid.x = NROWS/64 row tiles, grid.y = 3 (q/k/v section, 96 cols each)
// block = 256 threads, each computes 4x6 outputs. A,W tiles in dyn smem.
#define GEMM_SMEM ((64*100 + 96*100) * 4)
__global__ void qkv_gemm_kernel(const float* __restrict__ x,
                                const float* __restrict__ gt,
                                const float* __restrict__ W,
                                const float* __restrict__ bq) {
    extern __shared__ float sm[];
    float* Asm = sm;             // [64][100]
    float* Wsm = sm + 64*100;    // [96][100]
    const int tid  = threadIdx.x;
    const int row0 = blockIdx.x * 64;
    const int sec  = blockIdx.y;            // 0=q,1=k,2=v
    const int c0   = sec * 96;

    for (int idx = tid; idx < 64*96; idx += 256) {
        int r = idx / 96, k = idx % 96;
        int gr = row0 + r;
        int b = gr / NTOK, n = gr % NTOK;
        const float* src = (n == 0) ? (gt + (size_t)b*DIM)
                                    : (x + ((size_t)b*NQ + (n-1))*DIM);
        Asm[r*100 + k] = src[k];
    }
    for (int idx = tid; idx < 96*96; idx += 256) {
        int c = idx / 96, k = idx % 96;
        Wsm[c*100 + k] = W[(size_t)(c0 + c)*96 + k];
    }
    __syncthreads();

    const int tx = tid % 16;   // cols: tx*6 .. +5
    const int ty = tid / 16;   // rows: ty*4 .. +3
    float acc[4][6];
    #pragma unroll
    for (int i = 0; i < 4; ++i)
        #pragma unroll
        for (int j = 0; j < 6; ++j) acc[i][j] = 0.f;

    #pragma unroll 4
    for (int k = 0; k < 96; k += 4) {
        float4 a4[4], w4[6];
        #pragma unroll
        for (int i = 0; i < 4; ++i)
            a4[i] = *(const float4*)&Asm[(ty*4+i)*100 + k];
        #pragma unroll
        for (int j = 0; j < 6; ++j)
            w4[j] = *(const float4*)&Wsm[(tx*6+j)*100 + k];
        #pragma unroll
        for (int i = 0; i < 4; ++i)
            #pragma unroll
            for (int j = 0; j < 6; ++j)
                acc[i][j] += a4[i].x*w4[j].x + a4[i].y*w4[j].y
                           + a4[i].z*w4[j].z + a4[i].w*w4[j].w;
    }

    float* dst = (sec == 0) ? g_q : (sec == 1) ? g_k : g_v;
    #pragma unroll
    for (int i = 0; i < 4; ++i) {
        int gr = row0 + ty*4 + i;
        int b = gr / NTOK, n = gr % NTOK;
        #pragma unroll
        for (int j = 0; j < 6; ++j) {
            int cl = tx*6 + j;              // 0..95 within section
            int hh = cl / HD, dd = cl % HD;
            float v = acc[i][j] + bq[c0 + cl];
            dst[(((size_t)b*H + hh)*NTOK + n)*HD + dd] = v;
        }
    }
}

// ---------------- kernel 2: fused attention per (b,h) ----------------
// SMEM: K[344][33], V[344][33], P[8 warps][344][2]
#define KV_STRIDE 33
#define ATTN_SMEM ((2*NTOK*KV_STRIDE + 8*NTOK*2) * 4)
__global__ void attn_kernel(const float* __restrict__ mask) {
    extern __shared__ float sm[];
    float* Ksm = sm;
    float* Vsm = sm + NTOK*KV_STRIDE;
    float* Psm = Vsm + NTOK*KV_STRIDE;

    const int bh = blockIdx.x;
    const int b  = bh / H;
    const int h  = bh % H;
    const int w  = b % NW;
    const int tid  = threadIdx.x;
    const int wid  = tid >> 5;
    const int lane = tid & 31;
    const float scale = 0.17677669529663687f; // 32^-0.5

    const float* Kg = g_k + ((size_t)bh * NTOK) * HD;
    const float* Vg = g_v + ((size_t)bh * NTOK) * HD;
    const float* Qg = g_q + ((size_t)bh * NTOK) * HD;
    const float* biasH = g_bias + (size_t)h * NQ * NQ;
    const float* maskW = mask + (size_t)w * NQ * NQ;

    for (int idx = tid; idx < NTOK*HD; idx += 256) {
        int j = idx / HD, d = idx % HD;
        Ksm[j*KV_STRIDE + d] = Kg[idx];
        Vsm[j*KV_STRIDE + d] = Vg[idx];
    }
    __syncthreads();

    float* Pw = Psm + wid * NTOK * 2;

    for (int pair = wid; pair < NTOK/2; pair += 8) {
        const int n0 = 2*pair, n1 = n0 + 1;
        float q0[HD], q1[HD];
        #pragma unroll
        for (int d = 0; d < HD; ++d) {
            q0[d] = Qg[n0*HD + d] * scale;
            q1[d] = Qg[n1*HD + d] * scale;
        }

        float s0[11], s1[11];
        float m0 = -INFINITY, m1 = -INFINITY;
        #pragma unroll
        for (int t = 0; t < 11; ++t) {
            int j = t*32 + lane;
            if (j < NTOK) {
                const float* kp = &Ksm[j*KV_STRIDE];
                float a = 0.f, c = 0.f;
                #pragma unroll
                for (int d = 0; d < HD; ++d) {
                    float kv = kp[d];
                    a += q0[d]*kv; c += q1[d]*kv;
                }
                if (j > 0) {
                    int off = j - 1;
                    if (n0 > 0) a += biasH[(n0-1)*NQ + off] + maskW[(n0-1)*NQ + off];
                    c += biasH[(n1-1)*NQ + off] + maskW[(n1-1)*NQ + off];
                }
                s0[t] = a; s1[t] = c;
                m0 = fmaxf(m0, a); m1 = fmaxf(m1, c);
            } else { s0[t] = -INFINITY; s1[t] = -INFINITY; }
        }
        #pragma unroll
        for (int off = 16; off; off >>= 1) {
            m0 = fmaxf(m0, __shfl_xor_sync(0xffffffffu, m0, off));
            m1 = fmaxf(m1, __shfl_xor_sync(0xffffffffu, m1, off));
        }

        float sum0 = 0.f, sum1 = 0.f;
        #pragma unroll
        for (int t = 0; t < 11; ++t) {
            int j = t*32 + lane;
            if (j < NTOK) {
                float p0 = __expf(s0[t] - m0);
                float p1 = __expf(s1[t] - m1);
                sum0 += p0; sum1 += p1;
                Pw[j*2 + 0] = p0;
                Pw[j*2 + 1] = p1;
            }
        }
        #pragma unroll
        for (int off = 16; off; off >>= 1) {
            sum0 += __shfl_xor_sync(0xffffffffu, sum0, off);
            sum1 += __shfl_xor_sync(0xffffffffu, sum1, off);
        }
        float inv0 = 1.f / sum0, inv1 = 1.f / sum1;
        __syncwarp();

        // PV: lane = output dim d
        float o0 = 0.f, o1 = 0.f;
        #pragma unroll 4
        for (int j = 0; j < NTOK; j += 2) {
            float4 p = *(const float4*)&Pw[j*2];
            float va = Vsm[j*KV_STRIDE + lane];
            float vb = Vsm[(j+1)*KV_STRIDE + lane];
            o0 += p.x*va + p.z*vb;
            o1 += p.y*va + p.w*vb;
        }
        g_att[((size_t)b*NTOK + n0)*DIM + h*HD + lane] = o0 * inv0;
        g_att[((size_t)b*NTOK + n1)*DIM + h*HD + lane] = o1 * inv1;
        __syncwarp();
    }
}

// ---------------- kernel 3: proj + scatter ----------------
__global__ void proj_kernel(const float* __restrict__ W,
                            const float* __restrict__ bp,
                            float* __restrict__ dout) {
    extern __shared__ float sm[];
    float* Asm = sm;             // [64][100]
    float* Wsm = sm + 64*100;    // [96][100]
    const int tid  = threadIdx.x;
    const int row0 = blockIdx.x * 64;

    for (int idx = tid; idx < 64*96; idx += 256) {
        int r = idx / 96, k = idx % 96;
        Asm[r*100 + k] = g_att[(size_t)(row0 + r)*DIM + k];
    }
    for (int idx = tid; idx < 96*96; idx += 256) {
        int c = idx / 96, k = idx % 96;
        Wsm[c*100 + k] = W[(size_t)c*96 + k];
    }
    __syncthreads();

    const int tx = tid % 16;
    const int ty = tid / 16;
    float acc[4][6];
    #pragma unroll
    for (int i = 0; i < 4; ++i)
        #pragma unroll
        for (int j = 0; j < 6; ++j) acc[i][j] = 0.f;

    #pragma unroll 4
    for (int k = 0; k < 96; k += 4) {
        float4 a4[4], w4[6];
        #pragma unroll
        for (int i = 0; i < 4; ++i)
            a4[i] = *(const float4*)&Asm[(ty*4+i)*100 + k];
        #pragma unroll
        for (int j = 0; j < 6; ++j)
            w4[j] = *(const float4*)&Wsm[(tx*6+j)*100 + k];
        #pragma unroll
        for (int i = 0; i < 4; ++i)
            #pragma unroll
            for (int j = 0; j < 6; ++j)
                acc[i][j] += a4[i].x*w4[j].x + a4[i].y*w4[j].y
                           + a4[i].z*w4[j].z + a4[i].w*w4[j].w;
    }

    #pragma unroll
    for (int i = 0; i < 4; ++i) {
        int gr = row0 + ty*4 + i;
        int b = gr / NTOK, n = gr % NTOK;
        #pragma unroll
        for (int j = 0; j < 6; ++j) {
            int c = tx*6 + j;
            float v = acc[i][j] + bp[c];
            if (n == 0) dout[XOUT_SZ + (size_t)b*DIM + c] = v;          // gt_out
            else        dout[((size_t)b*NQ + (n-1))*DIM + c] = v;      // x_out
        }
    }
}

// ---------------- launch ----------------
extern "C" void kernel_launch(void* const* d_in, const int* in_sizes, int n_in,
                              void* d_out, int out_size) {
    const float* x     = (const float*)d_in[0];
    const float* gt    = (const float*)d_in[1];
    const float* mask  = (const float*)d_in[2];
    const int*   ri    = (const int*)  d_in[3];
    const float* Wqkv  = (const float*)d_in[4];
    const float* bqkv  = (const float*)d_in[5];
    const float* Wproj = (const float*)d_in[6];
    const float* bproj = (const float*)d_in[7];
    const float* btab  = (const float*)d_in[8];
    float* out = (float*)d_out;

    cudaFuncSetAttribute(qkv_gemm_kernel, cudaFuncAttributeMaxDynamicSharedMemorySize, GEMM_SMEM);
    cudaFuncSetAttribute(proj_kernel,     cudaFuncAttributeMaxDynamicSharedMemorySize, GEMM_SMEM);
    cudaFuncSetAttribute(attn_kernel,     cudaFuncAttributeMaxDynamicSharedMemorySize, ATTN_SMEM);

    bias_pre_kernel<<<(NQ*NQ + 255)/256, 256>>>(btab, ri);
    qkv_gemm_kernel<<<dim3(NROWS/64, 3), 256, GEMM_SMEM>>>(x, gt, Wqkv, bqkv);
    attn_kernel<<<B_*H, 256, ATTN_SMEM>>>(mask);
    proj_kernel<<<NROWS/64, 256, GEMM_SMEM>>>(Wproj, bproj, out);
}

// round 2
// speedup vs baseline: 1.0463x; 1.0463x over previous
#include <cuda_runtime.h>
#include <math.h>
#include <stdint.h>

// ---------------- problem constants ----------------
#define B_   512
#define NW   64
#define NQ   343
#define NTOK 344
#define DIM  96
#define H    3
#define HD   32
#define NROWS (B_*NTOK)
#define XOUT_SZ ((size_t)B_*NQ*DIM)

// ---------------- scratch ----------------
__device__ float g_q[(size_t)B_*H*NTOK*HD];
__device__ float g_k[(size_t)B_*H*NTOK*HD];
__device__ float g_v[(size_t)B_*H*NTOK*HD];
__device__ float g_att[(size_t)B_*NTOK*DIM];
__device__ float g_bm[(size_t)H*NW*NQ*NQ];   // bias[h] + mask[w], fused

// ---------------- kernel 0: bm = bias gather + mask ----------------
__global__ void bm_pre_kernel(const float* __restrict__ btab,
                              const int* __restrict__ ri,
                              const float* __restrict__ mask) {
    size_t gid = (size_t)blockIdx.x * 256 + threadIdx.x;
    if (gid >= (size_t)H*NW*NQ*NQ) return;
    int i  = (int)(gid % (NQ*NQ));
    int hw = (int)(gid / (NQ*NQ));
    int h = hw / NW, w = hw % NW;
    g_bm[gid] = btab[ri[i]*H + h] + mask[(size_t)w*NQ*NQ + i];
}

// ---------------- kernel 1: qkv = xc @ Wqkv^T + b ----------------
// 128-row x 96-col tiles, 256 threads, 8x6 thread tile.
#define GEMM_SMEM ((128*100 + 96*100) * 4)
__global__ void __launch_bounds__(256, 2)
qkv_gemm_kernel(const float* __restrict__ x,
                const float* __restrict__ gt,
                const float* __restrict__ W,
                const float* __restrict__ bq) {
    extern __shared__ float sm[];
    float* Asm = sm;              // [128][100]
    float* Wsm = sm + 128*100;    // [96][100]
    const int tid  = threadIdx.x;
    const int row0 = blockIdx.x * 128;
    const int sec  = blockIdx.y;
    const int c0   = sec * 96;

    for (int idx = tid; idx < 128*24; idx += 256) {
        int r = idx / 24, c4 = idx % 24;
        int gr = row0 + r;
        int b = gr / NTOK, n = gr % NTOK;
        const float* src = (n == 0) ? (gt + (size_t)b*DIM)
                                    : (x + ((size_t)b*NQ + (n-1))*DIM);
        *(float4*)&Asm[r*100 + c4*4] = *(const float4*)(src + c4*4);
    }
    for (int idx = tid; idx < 96*24; idx += 256) {
        int r = idx / 24, c4 = idx % 24;
        *(float4*)&Wsm[r*100 + c4*4] = *(const float4*)(W + (size_t)(c0+r)*96 + c4*4);
    }
    __syncthreads();

    const int tx = tid % 16;   // 6 cols
    const int ty = tid / 16;   // 8 rows
    float acc[8][6];
    #pragma unroll
    for (int i = 0; i < 8; ++i)
        #pragma unroll
        for (int j = 0; j < 6; ++j) acc[i][j] = 0.f;

    #pragma unroll 2
    for (int k = 0; k < 96; k += 4) {
        float4 a4[8], w4[6];
        #pragma unroll
        for (int i = 0; i < 8; ++i) a4[i] = *(const float4*)&Asm[(ty*8+i)*100 + k];
        #pragma unroll
        for (int j = 0; j < 6; ++j) w4[j] = *(const float4*)&Wsm[(tx*6+j)*100 + k];
        #pragma unroll
        for (int i = 0; i < 8; ++i)
            #pragma unroll
            for (int j = 0; j < 6; ++j)
                acc[i][j] += a4[i].x*w4[j].x + a4[i].y*w4[j].y
                           + a4[i].z*w4[j].z + a4[i].w*w4[j].w;
    }

    float* dst = (sec == 0) ? g_q : (sec == 1) ? g_k : g_v;
    #pragma unroll
    for (int i = 0; i < 8; ++i) {
        int gr = row0 + ty*8 + i;
        int b = gr / NTOK, n = gr % NTOK;
        #pragma unroll
        for (int j = 0; j < 6; ++j) {
            int cl = tx*6 + j;
            int hh = cl / HD, dd = cl % HD;
            dst[(((size_t)b*H + hh)*NTOK + n)*HD + dd] = acc[i][j] + bq[c0 + cl];
        }
    }
}

// ---------------- kernel 2: fused flash attention per (b,h) ----------------
// 11 warps; warp = 32-query strip; thread tile 4q x 8k (QK) and 4q x 8d (PV).
#define KT_STRIDE 356
#define PT_STRIDE 36
#define SM_KT 0
#define SM_QT 11392
#define SM_V  22784
#define SM_PT 34048
#define ATTN_SMEM ((SM_PT + 11*32*PT_STRIDE) * 4)   // 186880 B

__global__ void __launch_bounds__(352, 1) attn_kernel() {
    extern __shared__ float sm[];
    float* Kt = sm + SM_KT;    // [32][356]
    float* Qt = sm + SM_QT;    // [32][356] (pre-scaled)
    float* Vs = sm + SM_V;     // [352][32]

    const int bh = blockIdx.x;
    const int b  = bh / H;
    const int h  = bh % H;
    const int tid  = threadIdx.x;
    const int wid  = tid >> 5;
    const int lane = tid & 31;
    const float scale = 0.17677669529663687f;

    const float* Qg = g_q + (size_t)bh * NTOK * HD;
    const float* Kg = g_k + (size_t)bh * NTOK * HD;
    const float* Vg = g_v + (size_t)bh * NTOK * HD;
    const float* bmb = g_bm + ((size_t)(h*NW + (b % NW))) * NQ * NQ;

    // load + transpose K, Q; copy V
    for (int idx = tid; idx < NTOK*HD; idx += 352) {
        int n = idx >> 5, d = idx & 31;
        Kt[d*KT_STRIDE + n] = Kg[idx];
        Qt[d*KT_STRIDE + n] = Qg[idx] * scale;
        Vs[idx] = Vg[idx];
    }
    for (int idx = tid; idx < 32*12; idx += 352) {       // pad cols 344..355
        int d = idx / 12, c = 344 + idx % 12;
        Kt[d*KT_STRIDE + c] = 0.f;
        Qt[d*KT_STRIDE + c] = 0.f;
    }
    for (int idx = tid; idx < 8*32; idx += 352)          // pad V rows 344..351
        Vs[344*32 + idx] = 0.f;
    __syncthreads();

    const int g2 = lane >> 2;        // 0..7 q-group
    const int k2 = lane & 3;         // 0..3 k/d-group
    const int qb = wid*32 + g2*4;    // first of 4 queries
    const int db = k2*8;             // first of 8 dims / key offset
    float* Pt = sm + SM_PT + wid*32*PT_STRIDE;

    float o[4][8];
    float m[4], l[4];
    #pragma unroll
    for (int a = 0; a < 4; ++a) {
        m[a] = -1e30f; l[a] = 0.f;
        #pragma unroll
        for (int d = 0; d < 8; ++d) o[a][d] = 0.f;
    }

    #pragma unroll 1
    for (int kb = 0; kb < 11; ++kb) {
        const int kbase = kb*32;
        float s[4][8];
        #pragma unroll
        for (int a = 0; a < 4; ++a)
            #pragma unroll
            for (int c = 0; c < 8; ++c) s[a][c] = 0.f;

        const float* qp = Qt + qb;
        const float* kp = Kt + kbase + db;
        #pragma unroll 8
        for (int d = 0; d < 32; ++d) {
            float4 q4 = *(const float4*)(qp + d*KT_STRIDE);
            float4 ka = *(const float4*)(kp + d*KT_STRIDE);
            float4 kc = *(const float4*)(kp + d*KT_STRIDE + 4);
            float qv[4] = {q4.x, q4.y, q4.z, q4.w};
            float kv[8] = {ka.x, ka.y, ka.z, ka.w, kc.x, kc.y, kc.z, kc.w};
            #pragma unroll
            for (int a = 0; a < 4; ++a)
                #pragma unroll
                for (int c = 0; c < 8; ++c) s[a][c] += qv[a]*kv[c];
        }

        // bias+mask (rows n>=1, cols j>=1); kill padded keys
        #pragma unroll
        for (int a = 0; a < 4; ++a) {
            int n0 = qb + a;
            bool vq = (n0 >= 1) && (n0 < NTOK);
            const float* bmr = bmb + (size_t)(vq ? (n0-1) : 0) * NQ;
            #pragma unroll
            for (int c = 0; c < 8; ++c) {
                int j = kbase + db + c;
                if (j >= NTOK)          s[a][c] = -1e30f;
                else if (vq && j >= 1)  s[a][c] += __ldg(bmr + j - 1);
            }
        }

        // online softmax update
        #pragma unroll
        for (int a = 0; a < 4; ++a) {
            float mb = s[a][0];
            #pragma unroll
            for (int c = 1; c < 8; ++c) mb = fmaxf(mb, s[a][c]);
            mb = fmaxf(mb, __shfl_xor_sync(0xffffffffu, mb, 1));
            mb = fmaxf(mb, __shfl_xor_sync(0xffffffffu, mb, 2));
            float mn = fmaxf(m[a], mb);
            float alpha = __expf(m[a] - mn);
            m[a] = mn;
            l[a] *= alpha;
            #pragma unroll
            for (int d = 0; d < 8; ++d) o[a][d] *= alpha;
            #pragma unroll
            for (int c = 0; c < 8; ++c) {
                float p = __expf(s[a][c] - mn);
                l[a] += p;
                s[a][c] = p;
            }
        }

        // stage P transposed: Pt[j][q], float4 over q
        __syncwarp();
        #pragma unroll
        for (int c = 0; c < 8; ++c) {
            float4 pv = make_float4(s[0][c], s[1][c], s[2][c], s[3][c]);
            *(float4*)&Pt[(db + c)*PT_STRIDE + g2*4] = pv;
        }
        __syncwarp();

        // PV: O += P * V
        const float* vb0 = Vs + kbase*32 + db;
        #pragma unroll 4
        for (int j = 0; j < 32; ++j) {
            float4 p4 = *(const float4*)&Pt[j*PT_STRIDE + g2*4];
            float4 va = *(const float4*)(vb0 + j*32);
            float4 vc = *(const float4*)(vb0 + j*32 + 4);
            float pv[4] = {p4.x, p4.y, p4.z, p4.w};
            float vv[8] = {va.x, va.y, va.z, va.w, vc.x, vc.y, vc.z, vc.w};
            #pragma unroll
            for (int a = 0; a < 4; ++a)
                #pragma unroll
                for (int d = 0; d < 8; ++d) o[a][d] += pv[a]*vv[d];
        }
    }

    // normalize + store
    #pragma unroll
    for (int a = 0; a < 4; ++a) {
        float lt = l[a];
        lt += __shfl_xor_sync(0xffffffffu, lt, 1);
        lt += __shfl_xor_sync(0xffffffffu, lt, 2);
        float inv = 1.f / lt;
        int n0 = qb + a;
        if (n0 < NTOK) {
            float* dst = g_att + ((size_t)b*NTOK + n0)*DIM + h*HD + db;
            float4 w0 = make_float4(o[a][0]*inv, o[a][1]*inv, o[a][2]*inv, o[a][3]*inv);
            float4 w1 = make_float4(o[a][4]*inv, o[a][5]*inv, o[a][6]*inv, o[a][7]*inv);
            *(float4*)dst = w0;
            *(float4*)(dst+4) = w1;
        }
    }
}

// ---------------- kernel 3: proj + scatter ----------------
__global__ void __launch_bounds__(256, 2)
proj_kernel(const float* __restrict__ W,
            const float* __restrict__ bp,
            float* __restrict__ dout) {
    extern __shared__ float sm[];
    float* Asm = sm;              // [128][100]
    float* Wsm = sm + 128*100;    // [96][100]
    const int tid  = threadIdx.x;
    const int row0 = blockIdx.x * 128;

    for (int idx = tid; idx < 128*24; idx += 256) {
        int r = idx / 24, c4 = idx % 24;
        *(float4*)&Asm[r*100 + c4*4] =
            *(const float4*)(g_att + (size_t)(row0 + r)*DIM + c4*4);
    }
    for (int idx = tid; idx < 96*24; idx += 256) {
        int r = idx / 24, c4 = idx % 24;
        *(float4*)&Wsm[r*100 + c4*4] = *(const float4*)(W + (size_t)r*96 + c4*4);
    }
    __syncthreads();

    const int tx = tid % 16;
    const int ty = tid / 16;
    float acc[8][6];
    #pragma unroll
    for (int i = 0; i < 8; ++i)
        #pragma unroll
        for (int j = 0; j < 6; ++j) acc[i][j] = 0.f;

    #pragma unroll 2
    for (int k = 0; k < 96; k += 4) {
        float4 a4[8], w4[6];
        #pragma unroll
        for (int i = 0; i < 8; ++i) a4[i] = *(const float4*)&Asm[(ty*8+i)*100 + k];
        #pragma unroll
        for (int j = 0; j < 6; ++j) w4[j] = *(const float4*)&Wsm[(tx*6+j)*100 + k];
        #pragma unroll
        for (int i = 0; i < 8; ++i)
            #pragma unroll
            for (int j = 0; j < 6; ++j)
                acc[i][j] += a4[i].x*w4[j].x + a4[i].y*w4[j].y
                           + a4[i].z*w4[j].z + a4[i].w*w4[j].w;
    }

    #pragma unroll
    for (int i = 0; i < 8; ++i) {
        int gr = row0 + ty*8 + i;
        int b = gr / NTOK, n = gr % NTOK;
        #pragma unroll
        for (int j = 0; j < 6; ++j) {
            int c = tx*6 + j;
            float v = acc[i][j] + bp[c];
            if (n == 0) dout[XOUT_SZ + (size_t)b*DIM + c] = v;
            else        dout[((size_t)b*NQ + (n-1))*DIM + c] = v;
        }
    }
}

// ---------------- launch ----------------
extern "C" void kernel_launch(void* const* d_in, const int* in_sizes, int n_in,
                              void* d_out, int out_size) {
    const float* x     = (const float*)d_in[0];
    const float* gt    = (const float*)d_in[1];
    const float* mask  = (const float*)d_in[2];
    const int*   ri    = (const int*)  d_in[3];
    const float* Wqkv  = (const float*)d_in[4];
    const float* bqkv  = (const float*)d_in[5];
    const float* Wproj = (const float*)d_in[6];
    const float* bproj = (const float*)d_in[7];
    const float* btab  = (const float*)d_in[8];
    float* out = (float*)d_out;

    cudaFuncSetAttribute(qkv_gemm_kernel, cudaFuncAttributeMaxDynamicSharedMemorySize, GEMM_SMEM);
    cudaFuncSetAttribute(proj_kernel,     cudaFuncAttributeMaxDynamicSharedMemorySize, GEMM_SMEM);
    cudaFuncSetAttribute(attn_kernel,     cudaFuncAttributeMaxDynamicSharedMemorySize, ATTN_SMEM);

    {
        size_t total = (size_t)H*NW*NQ*NQ;
        bm_pre_kernel<<<(unsigned)((total + 255)/256), 256>>>(btab, ri, mask);
    }
    qkv_gemm_kernel<<<dim3(NROWS/128, 3), 256, GEMM_SMEM>>>(x, gt, Wqkv, bqkv);
    attn_kernel<<<B_*H, 352, ATTN_SMEM>>>();
    proj_kernel<<<NROWS/128, 256, GEMM_SMEM>>>(Wproj, bproj, out);
}

// round 3
// speedup vs baseline: 1.1264x; 1.0766x over previous
#include <cuda_runtime.h>
#include <math.h>
#include <stdint.h>

// ---------------- problem constants ----------------
#define B_   512
#define NW   64
#define NQ   343
#define NTOK 344
#define NP   352            // padded tokens (11*32)
#define DIM  96
#define H    3
#define HD   32
#define NROWS (B_*NTOK)
#define XOUT_SZ ((size_t)B_*NQ*DIM)

// ---------------- scratch ----------------
__device__ float g_q[(size_t)B_*H*NTOK*HD];
__device__ float g_k[(size_t)B_*H*NTOK*HD];
__device__ float g_v[(size_t)B_*H*NTOK*HD];
__device__ float g_att[(size_t)B_*NTOK*DIM];
__device__ float g_bm[(size_t)H*NW*NQ*NQ];   // bias[h] + mask[w], fused

// ---------------- kernel 0: bm = bias gather + mask ----------------
__global__ void bm_pre_kernel(const float* __restrict__ btab,
                              const int* __restrict__ ri,
                              const float* __restrict__ mask) {
    size_t gid = (size_t)blockIdx.x * 256 + threadIdx.x;
    if (gid >= (size_t)H*NW*NQ*NQ) return;
    int i  = (int)(gid % (NQ*NQ));
    int hw = (int)(gid / (NQ*NQ));
    int h = hw / NW, w = hw % NW;
    g_bm[gid] = btab[ri[i]*H + h] + mask[(size_t)w*NQ*NQ + i];
}

// ---------------- kernel 1: qkv = xc @ Wqkv^T + b ----------------
#define GEMM_SMEM ((128*100 + 96*100) * 4)
__global__ void __launch_bounds__(256, 2)
qkv_gemm_kernel(const float* __restrict__ x,
                const float* __restrict__ gt,
                const float* __restrict__ W,
                const float* __restrict__ bq) {
    extern __shared__ float sm[];
    float* Asm = sm;              // [128][100]
    float* Wsm = sm + 128*100;    // [96][100]
    const int tid  = threadIdx.x;
    const int row0 = blockIdx.x * 128;
    const int sec  = blockIdx.y;
    const int c0   = sec * 96;

    for (int idx = tid; idx < 128*24; idx += 256) {
        int r = idx / 24, c4 = idx % 24;
        int gr = row0 + r;
        int b = gr / NTOK, n = gr % NTOK;
        const float* src = (n == 0) ? (gt + (size_t)b*DIM)
                                    : (x + ((size_t)b*NQ + (n-1))*DIM);
        *(float4*)&Asm[r*100 + c4*4] = *(const float4*)(src + c4*4);
    }
    for (int idx = tid; idx < 96*24; idx += 256) {
        int r = idx / 24, c4 = idx % 24;
        *(float4*)&Wsm[r*100 + c4*4] = *(const float4*)(W + (size_t)(c0+r)*96 + c4*4);
    }
    __syncthreads();

    const int tx = tid % 16;
    const int ty = tid / 16;
    float acc[8][6];
    #pragma unroll
    for (int i = 0; i < 8; ++i)
        #pragma unroll
        for (int j = 0; j < 6; ++j) acc[i][j] = 0.f;

    #pragma unroll 2
    for (int k = 0; k < 96; k += 4) {
        float4 a4[8], w4[6];
        #pragma unroll
        for (int i = 0; i < 8; ++i) a4[i] = *(const float4*)&Asm[(ty*8+i)*100 + k];
        #pragma unroll
        for (int j = 0; j < 6; ++j) w4[j] = *(const float4*)&Wsm[(tx*6+j)*100 + k];
        #pragma unroll
        for (int i = 0; i < 8; ++i)
            #pragma unroll
            for (int j = 0; j < 6; ++j)
                acc[i][j] += a4[i].x*w4[j].x + a4[i].y*w4[j].y
                           + a4[i].z*w4[j].z + a4[i].w*w4[j].w;
    }

    float* dst = (sec == 0) ? g_q : (sec == 1) ? g_k : g_v;
    #pragma unroll
    for (int i = 0; i < 8; ++i) {
        int gr = row0 + ty*8 + i;
        int b = gr / NTOK, n = gr % NTOK;
        #pragma unroll
        for (int j = 0; j < 6; ++j) {
            int cl = tx*6 + j;
            int hh = cl / HD, dd = cl % HD;
            dst[(((size_t)b*H + hh)*NTOK + n)*HD + dd] = acc[i][j] + bq[c0 + cl];
        }
    }
}

// ---------------- kernel 2: tf32 tensor-core flash attention ----------------
// smem (floats): Qs[352][36] | Kt[32][360] | Vs[352][40] | Ps[11][32][36]
#define SM_QS 0
#define SM_KT 12672
#define SM_VS 24192
#define SM_PS 38272
#define ATTN_SMEM ((38272 + 11*32*36) * 4)   // 203776 B

__device__ __forceinline__ float tf32r(float x) {
    asm("cvt.rna.tf32.f32 %0, %1;" : "=f"(x) : "f"(x));
    return x;
}

#define MMA_TF32(d, a, b)                                                   \
    asm volatile("mma.sync.aligned.m16n8k8.row.col.f32.tf32.tf32.f32 "      \
        "{%0,%1,%2,%3},{%4,%5,%6,%7},{%8,%9},{%0,%1,%2,%3};"                \
        : "+f"(d[0]), "+f"(d[1]), "+f"(d[2]), "+f"(d[3])                     \
        : "r"(a[0]), "r"(a[1]), "r"(a[2]), "r"(a[3]), "r"(b[0]), "r"(b[1]))

__global__ void __launch_bounds__(352, 1) attn_kernel() {
    extern __shared__ float sm[];
    float* Qs = sm + SM_QS;    // [352][36]  tf32, pre-scaled
    float* Kt = sm + SM_KT;    // [32][360]  tf32 transposed
    float* Vs = sm + SM_VS;    // [352][40]  tf32
    const uint32_t* Qsu = (const uint32_t*)Qs;
    const uint32_t* Ktu = (const uint32_t*)Kt;
    const uint32_t* Vsu = (const uint32_t*)Vs;

    const int bh = blockIdx.x;
    const int b  = bh / H;
    const int h  = bh % H;
    const int tid  = threadIdx.x;
    const int wid  = tid >> 5;
    const int lane = tid & 31;
    const int g    = lane >> 2;     // 0..7
    const int tg   = lane & 3;      // 0..3
    const float scale = 0.17677669529663687f;

    const float* Qg = g_q + (size_t)bh * NTOK * HD;
    const float* Kg = g_k + (size_t)bh * NTOK * HD;
    const float* Vg = g_v + (size_t)bh * NTOK * HD;
    const float* bmb = g_bm + ((size_t)(h*NW + (b % NW))) * NQ * NQ;

    // fill smem (tf32-rounded)
    for (int idx = tid; idx < NP*HD; idx += 352) {
        int n = idx >> 5, d = idx & 31;
        float qv = 0.f, kv = 0.f, vv = 0.f;
        if (n < NTOK) {
            qv = Qg[idx] * scale;
            kv = Kg[idx];
            vv = Vg[idx];
        }
        Qs[n*36 + d]  = tf32r(qv);
        Kt[d*360 + n] = tf32r(kv);
        Vs[n*40 + d]  = tf32r(vv);
    }
    __syncthreads();

    const int qrow0 = wid*32 + g;        // this thread's base query row
    float* Pw = sm + SM_PS + wid*32*36;
    const uint32_t* Pwu = (const uint32_t*)Pw;

    // hoist Q fragments: qf[mtile][ktile][4]
    uint32_t qf[2][4][4];
    #pragma unroll
    for (int mt = 0; mt < 2; ++mt)
        #pragma unroll
        for (int kt = 0; kt < 4; ++kt) {
            int r = wid*32 + mt*16 + g;
            qf[mt][kt][0] = Qsu[r*36 + kt*8 + tg];
            qf[mt][kt][1] = Qsu[(r+8)*36 + kt*8 + tg];
            qf[mt][kt][2] = Qsu[r*36 + kt*8 + tg + 4];
            qf[mt][kt][3] = Qsu[(r+8)*36 + kt*8 + tg + 4];
        }

    float o[2][4][4];
    float m[2][2], l[2][2];
    #pragma unroll
    for (int mt = 0; mt < 2; ++mt) {
        m[mt][0] = -1e30f; m[mt][1] = -1e30f;
        l[mt][0] = 0.f;    l[mt][1] = 0.f;
        #pragma unroll
        for (int nt = 0; nt < 4; ++nt)
            #pragma unroll
            for (int e = 0; e < 4; ++e) o[mt][nt][e] = 0.f;
    }

    #pragma unroll 1
    for (int kb = 0; kb < 11; ++kb) {
        const int kbase = kb*32;

        // ---- S = Q K^T ----
        float s[2][4][4];
        #pragma unroll
        for (int mt = 0; mt < 2; ++mt)
            #pragma unroll
            for (int nt = 0; nt < 4; ++nt)
                #pragma unroll
                for (int e = 0; e < 4; ++e) s[mt][nt][e] = 0.f;

        #pragma unroll
        for (int kt = 0; kt < 4; ++kt) {
            uint32_t bb[4][2];
            #pragma unroll
            for (int nt = 0; nt < 4; ++nt) {
                const uint32_t* bp = Ktu + (kt*8 + tg)*360 + kbase + nt*8 + g;
                bb[nt][0] = bp[0];
                bb[nt][1] = bp[4*360];
            }
            #pragma unroll
            for (int mt = 0; mt < 2; ++mt)
                #pragma unroll
                for (int nt = 0; nt < 4; ++nt)
                    MMA_TF32(s[mt][nt], qf[mt][kt], bb[nt]);
        }

        // ---- bias + mask + key padding ----
        #pragma unroll
        for (int mt = 0; mt < 2; ++mt)
            #pragma unroll
            for (int rr = 0; rr < 2; ++rr) {
                int n0 = qrow0 + mt*16 + rr*8;
                bool vq = (n0 >= 1) && (n0 < NTOK);
                const float* bmrow = bmb + (size_t)(vq ? (n0-1) : 0) * NQ;
                #pragma unroll
                for (int nt = 0; nt < 4; ++nt)
                    #pragma unroll
                    for (int e = 0; e < 2; ++e) {
                        int j = kbase + nt*8 + 2*tg + e;
                        float& sv = s[mt][nt][rr*2 + e];
                        if (j >= NTOK)          sv = -1e30f;
                        else if (vq && j >= 1)  sv += __ldg(bmrow + j - 1);
                    }
            }

        // ---- online softmax (per row) ----
        #pragma unroll
        for (int mt = 0; mt < 2; ++mt)
            #pragma unroll
            for (int rr = 0; rr < 2; ++rr) {
                float mb = -1e30f;
                #pragma unroll
                for (int nt = 0; nt < 4; ++nt) {
                    mb = fmaxf(mb, s[mt][nt][rr*2]);
                    mb = fmaxf(mb, s[mt][nt][rr*2+1]);
                }
                mb = fmaxf(mb, __shfl_xor_sync(0xffffffffu, mb, 1));
                mb = fmaxf(mb, __shfl_xor_sync(0xffffffffu, mb, 2));
                float mo = m[mt][rr];
                float mn = fmaxf(mo, mb);
                float alpha = __expf(mo - mn);
                m[mt][rr] = mn;
                float lv = l[mt][rr] * alpha;
                #pragma unroll
                for (int nt = 0; nt < 4; ++nt) {
                    o[mt][nt][rr*2]   *= alpha;
                    o[mt][nt][rr*2+1] *= alpha;
                }
                #pragma unroll
                for (int nt = 0; nt < 4; ++nt)
                    #pragma unroll
                    for (int e = 0; e < 2; ++e) {
                        float p = __expf(s[mt][nt][rr*2+e] - mn);
                        lv += p;
                        s[mt][nt][rr*2+e] = p;
                    }
                l[mt][rr] = lv;
            }

        // ---- stage P (C-frag layout -> smem) ----
        __syncwarp();
        #pragma unroll
        for (int mt = 0; mt < 2; ++mt)
            #pragma unroll
            for (int rr = 0; rr < 2; ++rr) {
                int r = mt*16 + g + rr*8;
                #pragma unroll
                for (int nt = 0; nt < 4; ++nt)
                    *(float2*)&Pw[r*36 + nt*8 + 2*tg] =
                        make_float2(s[mt][nt][rr*2], s[mt][nt][rr*2+1]);
            }
        __syncwarp();

        // ---- O += P V ----
        #pragma unroll
        for (int jt = 0; jt < 4; ++jt) {
            uint32_t af[2][4];
            #pragma unroll
            for (int mt = 0; mt < 2; ++mt) {
                int r = mt*16 + g;
                af[mt][0] = Pwu[r*36 + jt*8 + tg];
                af[mt][1] = Pwu[(r+8)*36 + jt*8 + tg];
                af[mt][2] = Pwu[r*36 + jt*8 + tg + 4];
                af[mt][3] = Pwu[(r+8)*36 + jt*8 + tg + 4];
            }
            uint32_t vb[4][2];
            #pragma unroll
            for (int nt = 0; nt < 4; ++nt) {
                const uint32_t* vp = Vsu + (kbase + jt*8 + tg)*40 + nt*8 + g;
                vb[nt][0] = vp[0];
                vb[nt][1] = vp[4*40];
            }
            #pragma unroll
            for (int mt = 0; mt < 2; ++mt)
                #pragma unroll
                for (int nt = 0; nt < 4; ++nt)
                    MMA_TF32(o[mt][nt], af[mt], vb[nt]);
        }
    }

    // ---- normalize + store ----
    #pragma unroll
    for (int mt = 0; mt < 2; ++mt)
        #pragma unroll
        for (int rr = 0; rr < 2; ++rr) {
            float lv = l[mt][rr];
            lv += __shfl_xor_sync(0xffffffffu, lv, 1);
            lv += __shfl_xor_sync(0xffffffffu, lv, 2);
            float inv = 1.f / lv;
            int n0 = qrow0 + mt*16 + rr*8;
            if (n0 < NTOK) {
                float* dst = g_att + ((size_t)b*NTOK + n0)*DIM + h*HD;
                #pragma unroll
                for (int nt = 0; nt < 4; ++nt)
                    *(float2*)(dst + nt*8 + 2*tg) =
                        make_float2(o[mt][nt][rr*2]*inv, o[mt][nt][rr*2+1]*inv);
            }
        }
}

// ---------------- kernel 3: proj + scatter ----------------
__global__ void __launch_bounds__(256, 2)
proj_kernel(const float* __restrict__ W,
            const float* __restrict__ bp,
            float* __restrict__ dout) {
    extern __shared__ float sm[];
    float* Asm = sm;              // [128][100]
    float* Wsm = sm + 128*100;    // [96][100]
    const int tid  = threadIdx.x;
    const int row0 = blockIdx.x * 128;

    for (int idx = tid; idx < 128*24; idx += 256) {
        int r = idx / 24, c4 = idx % 24;
        *(float4*)&Asm[r*100 + c4*4] =
            *(const float4*)(g_att + (size_t)(row0 + r)*DIM + c4*4);
    }
    for (int idx = tid; idx < 96*24; idx += 256) {
        int r = idx / 24, c4 = idx % 24;
        *(float4*)&Wsm[r*100 + c4*4] = *(const float4*)(W + (size_t)r*96 + c4*4);
    }
    __syncthreads();

    const int tx = tid % 16;
    const int ty = tid / 16;
    float acc[8][6];
    #pragma unroll
    for (int i = 0; i < 8; ++i)
        #pragma unroll
        for (int j = 0; j < 6; ++j) acc[i][j] = 0.f;

    #pragma unroll 2
    for (int k = 0; k < 96; k += 4) {
        float4 a4[8], w4[6];
        #pragma unroll
        for (int i = 0; i < 8; ++i) a4[i] = *(const float4*)&Asm[(ty*8+i)*100 + k];
        #pragma unroll
        for (int j = 0; j < 6; ++j) w4[j] = *(const float4*)&Wsm[(tx*6+j)*100 + k];
        #pragma unroll
        for (int i = 0; i < 8; ++i)
            #pragma unroll
            for (int j = 0; j < 6; ++j)
                acc[i][j] += a4[i].x*w4[j].x + a4[i].y*w4[j].y
                           + a4[i].z*w4[j].z + a4[i].w*w4[j].w;
    }

    #pragma unroll
    for (int i = 0; i < 8; ++i) {
        int gr = row0 + ty*8 + i;
        int b = gr / NTOK, n = gr % NTOK;
        #pragma unroll
        for (int j = 0; j < 6; ++j) {
            int c = tx*6 + j;
            float v = acc[i][j] + bp[c];
            if (n == 0) dout[XOUT_SZ + (size_t)b*DIM + c] = v;
            else        dout[((size_t)b*NQ + (n-1))*DIM + c] = v;
        }
    }
}

// ---------------- launch ----------------
extern "C" void kernel_launch(void* const* d_in, const int* in_sizes, int n_in,
                              void* d_out, int out_size) {
    const float* x     = (const float*)d_in[0];
    const float* gt    = (const float*)d_in[1];
    const float* mask  = (const float*)d_in[2];
    const int*   ri    = (const int*)  d_in[3];
    const float* Wqkv  = (const float*)d_in[4];
    const float* bqkv  = (const float*)d_in[5];
    const float* Wproj = (const float*)d_in[6];
    const float* bproj = (const float*)d_in[7];
    const float* btab  = (const float*)d_in[8];
    float* out = (float*)d_out;

    cudaFuncSetAttribute(qkv_gemm_kernel, cudaFuncAttributeMaxDynamicSharedMemorySize, GEMM_SMEM);
    cudaFuncSetAttribute(proj_kernel,     cudaFuncAttributeMaxDynamicSharedMemorySize, GEMM_SMEM);
    cudaFuncSetAttribute(attn_kernel,     cudaFuncAttributeMaxDynamicSharedMemorySize, ATTN_SMEM);

    {
        size_t total = (size_t)H*NW*NQ*NQ;
        bm_pre_kernel<<<(unsigned)((total + 255)/256), 256>>>(btab, ri, mask);
    }
    qkv_gemm_kernel<<<dim3(NROWS/128, 3), 256, GEMM_SMEM>>>(x, gt, Wqkv, bqkv);
    attn_kernel<<<B_*H, 352, ATTN_SMEM>>>();
    proj_kernel<<<NROWS/128, 256, GEMM_SMEM>>>(Wproj, bproj, out);
}

// round 4
// speedup vs baseline: 1.1939x; 1.0599x over previous
#include <cuda_runtime.h>
#include <math.h>
#include <stdint.h>

// ---------------- problem constants ----------------
#define B_   512
#define NW   64
#define NQ   343
#define NTOK 344
#define NP   352            // padded tokens (11*32)
#define DIM  96
#define H    3
#define HD   32
#define NROWS (B_*NTOK)
#define XOUT_SZ ((size_t)B_*NQ*DIM)

// ---------------- scratch ----------------
__device__ float g_q[(size_t)B_*H*NTOK*HD];
__device__ float g_k[(size_t)B_*H*NTOK*HD];
__device__ float g_v[(size_t)B_*H*NTOK*HD];
__device__ float g_att[(size_t)B_*NTOK*DIM];
__device__ float g_bm[(size_t)H*NW*NQ*NQ];   // bias[h] + mask[w], fused

// ---------------- kernel 0: bm = bias gather + mask ----------------
__global__ void bm_pre_kernel(const float* __restrict__ btab,
                              const int* __restrict__ ri,
                              const float* __restrict__ mask) {
    size_t gid = (size_t)blockIdx.x * 256 + threadIdx.x;
    if (gid >= (size_t)H*NW*NQ*NQ) return;
    int i  = (int)(gid % (NQ*NQ));
    int hw = (int)(gid / (NQ*NQ));
    int h = hw / NW, w = hw % NW;
    g_bm[gid] = btab[ri[i]*H + h] + mask[(size_t)w*NQ*NQ + i];
}

// ---------------- kernel 1: qkv = xc @ Wqkv^T + b ----------------
#define GEMM_SMEM ((128*100 + 96*100) * 4)
__global__ void __launch_bounds__(256, 2)
qkv_gemm_kernel(const float* __restrict__ x,
                const float* __restrict__ gt,
                const float* __restrict__ W,
                const float* __restrict__ bq) {
    extern __shared__ float sm[];
    float* Asm = sm;              // [128][100]
    float* Wsm = sm + 128*100;    // [96][100]
    const int tid  = threadIdx.x;
    const int row0 = blockIdx.x * 128;
    const int sec  = blockIdx.y;
    const int c0   = sec * 96;

    for (int idx = tid; idx < 128*24; idx += 256) {
        int r = idx / 24, c4 = idx % 24;
        int gr = row0 + r;
        int b = gr / NTOK, n = gr % NTOK;
        const float* src = (n == 0) ? (gt + (size_t)b*DIM)
                                    : (x + ((size_t)b*NQ + (n-1))*DIM);
        *(float4*)&Asm[r*100 + c4*4] = *(const float4*)(src + c4*4);
    }
    for (int idx = tid; idx < 96*24; idx += 256) {
        int r = idx / 24, c4 = idx % 24;
        *(float4*)&Wsm[r*100 + c4*4] = *(const float4*)(W + (size_t)(c0+r)*96 + c4*4);
    }
    __syncthreads();

    const int tx = tid % 16;
    const int ty = tid / 16;
    float acc[8][6];
    #pragma unroll
    for (int i = 0; i < 8; ++i)
        #pragma unroll
        for (int j = 0; j < 6; ++j) acc[i][j] = 0.f;

    #pragma unroll 2
    for (int k = 0; k < 96; k += 4) {
        float4 a4[8], w4[6];
        #pragma unroll
        for (int i = 0; i < 8; ++i) a4[i] = *(const float4*)&Asm[(ty*8+i)*100 + k];
        #pragma unroll
        for (int j = 0; j < 6; ++j) w4[j] = *(const float4*)&Wsm[(tx*6+j)*100 + k];
        #pragma unroll
        for (int i = 0; i < 8; ++i)
            #pragma unroll
            for (int j = 0; j < 6; ++j)
                acc[i][j] += a4[i].x*w4[j].x + a4[i].y*w4[j].y
                           + a4[i].z*w4[j].z + a4[i].w*w4[j].w;
    }

    float* dst = (sec == 0) ? g_q : (sec == 1) ? g_k : g_v;
    #pragma unroll
    for (int i = 0; i < 8; ++i) {
        int gr = row0 + ty*8 + i;
        int b = gr / NTOK, n = gr % NTOK;
        #pragma unroll
        for (int j = 0; j < 6; ++j) {
            int cl = tx*6 + j;
            int hh = cl / HD, dd = cl % HD;
            dst[(((size_t)b*H + hh)*NTOK + n)*HD + dd] = acc[i][j] + bq[c0 + cl];
        }
    }
}

// ---------------- kernel 2: tf32 tensor-core flash attention ----------------
// 22 warps, each owns a 16-query strip. No online max (logits bounded).
// smem (floats): Qs[352][36] | Kt[32][360] | Vs[352][40] | Ps[22][16][36]
#define SM_QS 0
#define SM_KT 12672
#define SM_VS 24192
#define SM_PS 38272
#define ATTN_SMEM ((38272 + 22*16*36) * 4)   // 203776 B

__device__ __forceinline__ float tf32r(float x) {
    asm("cvt.rna.tf32.f32 %0, %1;" : "=f"(x) : "f"(x));
    return x;
}

#define MMA_TF32(d, a, b)                                                   \
    asm volatile("mma.sync.aligned.m16n8k8.row.col.f32.tf32.tf32.f32 "      \
        "{%0,%1,%2,%3},{%4,%5,%6,%7},{%8,%9},{%0,%1,%2,%3};"                \
        : "+f"(d[0]), "+f"(d[1]), "+f"(d[2]), "+f"(d[3])                     \
        : "r"(a[0]), "r"(a[1]), "r"(a[2]), "r"(a[3]), "r"(b[0]), "r"(b[1]))

__global__ void __launch_bounds__(704, 1) attn_kernel() {
    extern __shared__ float sm[];
    float* Qs = sm + SM_QS;    // [352][36]  tf32, pre-scaled
    float* Kt = sm + SM_KT;    // [32][360]  tf32 transposed
    float* Vs = sm + SM_VS;    // [352][40]  tf32
    const uint32_t* Qsu = (const uint32_t*)Qs;
    const uint32_t* Ktu = (const uint32_t*)Kt;
    const uint32_t* Vsu = (const uint32_t*)Vs;

    const int bh = blockIdx.x;
    const int b  = bh / H;
    const int h  = bh % H;
    const int tid  = threadIdx.x;
    const int wid  = tid >> 5;
    const int lane = tid & 31;
    const int g    = lane >> 2;     // 0..7
    const int tg   = lane & 3;      // 0..3
    const float scale = 0.17677669529663687f;

    const float* Qg = g_q + (size_t)bh * NTOK * HD;
    const float* Kg = g_k + (size_t)bh * NTOK * HD;
    const float* Vg = g_v + (size_t)bh * NTOK * HD;
    const float* bmb = g_bm + ((size_t)(h*NW + (b % NW))) * NQ * NQ;

    // fill smem (tf32-rounded); rows >= NTOK zero-padded
    for (int idx = tid; idx < NP*HD; idx += 704) {
        int n = idx >> 5, d = idx & 31;
        float qv = 0.f, kv = 0.f, vv = 0.f;
        if (n < NTOK) {
            qv = Qg[idx] * scale;
            kv = Kg[idx];
            vv = Vg[idx];
        }
        Qs[n*36 + d]  = tf32r(qv);
        Kt[d*360 + n] = tf32r(kv);
        Vs[n*40 + d]  = tf32r(vv);
    }
    __syncthreads();

    const int qrow0 = wid*16 + g;        // this thread's base query row
    float* Pw = sm + SM_PS + wid*16*36;
    const uint32_t* Pwu = (const uint32_t*)Pw;

    // hoist Q fragments: qf[ktile][4]
    uint32_t qf[4][4];
    {
        const int r = wid*16 + g;
        #pragma unroll
        for (int kt = 0; kt < 4; ++kt) {
            qf[kt][0] = Qsu[r*36 + kt*8 + tg];
            qf[kt][1] = Qsu[(r+8)*36 + kt*8 + tg];
            qf[kt][2] = Qsu[r*36 + kt*8 + tg + 4];
            qf[kt][3] = Qsu[(r+8)*36 + kt*8 + tg + 4];
        }
    }

    float o[4][4];
    float l[2] = {0.f, 0.f};
    #pragma unroll
    for (int nt = 0; nt < 4; ++nt)
        #pragma unroll
        for (int e = 0; e < 4; ++e) o[nt][e] = 0.f;

    #pragma unroll 1
    for (int kb = 0; kb < 11; ++kb) {
        const int kbase = kb*32;

        // ---- S = Q K^T ----
        float s[4][4];
        #pragma unroll
        for (int nt = 0; nt < 4; ++nt)
            #pragma unroll
            for (int e = 0; e < 4; ++e) s[nt][e] = 0.f;

        #pragma unroll
        for (int kt = 0; kt < 4; ++kt) {
            uint32_t bb[4][2];
            #pragma unroll
            for (int nt = 0; nt < 4; ++nt) {
                const uint32_t* bp = Ktu + (kt*8 + tg)*360 + kbase + nt*8 + g;
                bb[nt][0] = bp[0];
                bb[nt][1] = bp[4*360];
            }
            #pragma unroll
            for (int nt = 0; nt < 4; ++nt)
                MMA_TF32(s[nt], qf[kt], bb[nt]);
        }

        // ---- bias+mask + exp (no max subtraction; logits bounded) ----
        #pragma unroll
        for (int rr = 0; rr < 2; ++rr) {
            int n0 = qrow0 + rr*8;
            bool vq = (n0 >= 1) && (n0 < NTOK);
            const float* bmrow = bmb + (size_t)(vq ? (n0-1) : 0) * NQ;
            float lv = 0.f;
            #pragma unroll
            for (int nt = 0; nt < 4; ++nt)
                #pragma unroll
                for (int e = 0; e < 2; ++e) {
                    int j = kbase + nt*8 + 2*tg + e;
                    float p;
                    if (j >= NTOK) p = 0.f;
                    else {
                        float add = (vq && j >= 1) ? __ldg(bmrow + j - 1) : 0.f;
                        p = __expf(s[nt][rr*2+e] + add);
                    }
                    lv += p;
                    s[nt][rr*2+e] = p;
                }
            l[rr] += lv;
        }

        // ---- stage P (C-frag layout -> smem) ----
        __syncwarp();
        #pragma unroll
        for (int rr = 0; rr < 2; ++rr) {
            int r = g + rr*8;
            #pragma unroll
            for (int nt = 0; nt < 4; ++nt)
                *(float2*)&Pw[r*36 + nt*8 + 2*tg] =
                    make_float2(s[nt][rr*2], s[nt][rr*2+1]);
        }
        __syncwarp();

        // ---- O += P V ----
        #pragma unroll
        for (int jt = 0; jt < 4; ++jt) {
            uint32_t af[4];
            af[0] = Pwu[g*36 + jt*8 + tg];
            af[1] = Pwu[(g+8)*36 + jt*8 + tg];
            af[2] = Pwu[g*36 + jt*8 + tg + 4];
            af[3] = Pwu[(g+8)*36 + jt*8 + tg + 4];
            uint32_t vb[4][2];
            #pragma unroll
            for (int nt = 0; nt < 4; ++nt) {
                const uint32_t* vp = Vsu + (kbase + jt*8 + tg)*40 + nt*8 + g;
                vb[nt][0] = vp[0];
                vb[nt][1] = vp[4*40];
            }
            #pragma unroll
            for (int nt = 0; nt < 4; ++nt)
                MMA_TF32(o[nt], af, vb[nt]);
        }
    }

    // ---- normalize + store ----
    #pragma unroll
    for (int rr = 0; rr < 2; ++rr) {
        float lv = l[rr];
        lv += __shfl_xor_sync(0xffffffffu, lv, 1);
        lv += __shfl_xor_sync(0xffffffffu, lv, 2);
        float inv = 1.f / lv;
        int n0 = qrow0 + rr*8;
        if (n0 < NTOK) {
            float* dst = g_att + ((size_t)b*NTOK + n0)*DIM + h*HD;
            #pragma unroll
            for (int nt = 0; nt < 4; ++nt)
                *(float2*)(dst + nt*8 + 2*tg) =
                    make_float2(o[nt][rr*2]*inv, o[nt][rr*2+1]*inv);
        }
    }
}

// ---------------- kernel 3: proj + scatter ----------------
__global__ void __launch_bounds__(256, 2)
proj_kernel(const float* __restrict__ W,
            const float* __restrict__ bp,
            float* __restrict__ dout) {
    extern __shared__ float sm[];
    float* Asm = sm;              // [128][100]
    float* Wsm = sm + 128*100;    // [96][100]
    const int tid  = threadIdx.x;
    const int row0 = blockIdx.x * 128;

    for (int idx = tid; idx < 128*24; idx += 256) {
        int r = idx / 24, c4 = idx % 24;
        *(float4*)&Asm[r*100 + c4*4] =
            *(const float4*)(g_att + (size_t)(row0 + r)*DIM + c4*4);
    }
    for (int idx = tid; idx < 96*24; idx += 256) {
        int r = idx / 24, c4 = idx % 24;
        *(float4*)&Wsm[r*100 + c4*4] = *(const float4*)(W + (size_t)r*96 + c4*4);
    }
    __syncthreads();

    const int tx = tid % 16;
    const int ty = tid / 16;
    float acc[8][6];
    #pragma unroll
    for (int i = 0; i < 8; ++i)
        #pragma unroll
        for (int j = 0; j < 6; ++j) acc[i][j] = 0.f;

    #pragma unroll 2
    for (int k = 0; k < 96; k += 4) {
        float4 a4[8], w4[6];
        #pragma unroll
        for (int i = 0; i < 8; ++i) a4[i] = *(const float4*)&Asm[(ty*8+i)*100 + k];
        #pragma unroll
        for (int j = 0; j < 6; ++j) w4[j] = *(const float4*)&Wsm[(tx*6+j)*100 + k];
        #pragma unroll
        for (int i = 0; i < 8; ++i)
            #pragma unroll
            for (int j = 0; j < 6; ++j)
                acc[i][j] += a4[i].x*w4[j].x + a4[i].y*w4[j].y
                           + a4[i].z*w4[j].z + a4[i].w*w4[j].w;
    }

    #pragma unroll
    for (int i = 0; i < 8; ++i) {
        int gr = row0 + ty*8 + i;
        int b = gr / NTOK, n = gr % NTOK;
        #pragma unroll
        for (int j = 0; j < 6; ++j) {
            int c = tx*6 + j;
            float v = acc[i][j] + bp[c];
            if (n == 0) dout[XOUT_SZ + (size_t)b*DIM + c] = v;
            else        dout[((size_t)b*NQ + (n-1))*DIM + c] = v;
        }
    }
}

// ---------------- launch ----------------
extern "C" void kernel_launch(void* const* d_in, const int* in_sizes, int n_in,
                              void* d_out, int out_size) {
    const float* x     = (const float*)d_in[0];
    const float* gt    = (const float*)d_in[1];
    const float* mask  = (const float*)d_in[2];
    const int*   ri    = (const int*)  d_in[3];
    const float* Wqkv  = (const float*)d_in[4];
    const float* bqkv  = (const float*)d_in[5];
    const float* Wproj = (const float*)d_in[6];
    const float* bproj = (const float*)d_in[7];
    const float* btab  = (const float*)d_in[8];
    float* out = (float*)d_out;

    cudaFuncSetAttribute(qkv_gemm_kernel, cudaFuncAttributeMaxDynamicSharedMemorySize, GEMM_SMEM);
    cudaFuncSetAttribute(proj_kernel,     cudaFuncAttributeMaxDynamicSharedMemorySize, GEMM_SMEM);
    cudaFuncSetAttribute(attn_kernel,     cudaFuncAttributeMaxDynamicSharedMemorySize, ATTN_SMEM);

    {
        size_t total = (size_t)H*NW*NQ*NQ;
        bm_pre_kernel<<<(unsigned)((total + 255)/256), 256>>>(btab, ri, mask);
    }
    qkv_gemm_kernel<<<dim3(NROWS/128, 3), 256, GEMM_SMEM>>>(x, gt, Wqkv, bqkv);
    attn_kernel<<<B_*H, 704, ATTN_SMEM>>>();
    proj_kernel<<<NROWS/128, 256, GEMM_SMEM>>>(Wproj, bproj, out);
}